// round 14
// baseline (speedup 1.0000x reference)
#include <cuda_runtime.h>

// Problem constants
#define BB  2048   // batch
#define TT  2      // timesteps
#define NZ  100    // zones
#define SS  6      // state
#define HH  64     // hidden (actor + critic)
#define G3  192    // 3*H gate rows
#define NBF 35     // neighbor feature size
#define LMH 128    // localized module hidden
#define ATH 256    // actor threads per CTA == batch tile (256 => 255-reg budget)
#define CW  16     // critic warps per CTA
// padded strides (critic SMEM, kill 32-way write conflicts)
#define G3P 193
#define HHP 65
#define LMP 129

typedef unsigned long long ull;

// Actor output scratch, layout Aflat[n*(B*T) + b*T + t]  (== flatten of [N,B,T])
//   p[b,t,n] = Aflat[200*b + 100*t + n]
// The reshape scramble makes EVERY Aflat entry live in output 0 (R8 lesson).
// Fused p-output inverse map: element F=4096n+2b+t is out_p[F/200, F%100]
// iff (F/100) is odd.
__device__ float g_Aflat[NZ * BB * TT];

__device__ __forceinline__ float fsig(float x) {
    return __fdividef(1.0f, 1.0f + __expf(-x));
}
__device__ __forceinline__ float ftanh(float x) {
    return 1.0f - __fdividef(2.0f, __expf(2.0f * x) + 1.0f);
}
// packed f32x2 helpers (Blackwell)
__device__ __forceinline__ ull pk(float a, float b) {
    ull r; asm("mov.b64 %0,{%1,%2};" : "=l"(r) : "f"(a), "f"(b)); return r;
}
__device__ __forceinline__ float2 upk(ull v) {
    float2 r; asm("mov.b64 {%0,%1},%2;" : "=f"(r.x), "=f"(r.y) : "l"(v)); return r;
}
__device__ __forceinline__ ull ffma2(ull a, ull b, ull c) {   // a*b+c, 2 lanes
    ull d; asm("fma.rn.f32x2 %0,%1,%2,%3;" : "=l"(d) : "l"(a), "l"(b), "l"(c)); return d;
}
__device__ __forceinline__ ull fadd2(ull a, ull b) {
    ull d; asm("add.rn.f32x2 %0,%1,%2;" : "=l"(d) : "l"(a), "l"(b)); return d;
}
__device__ __forceinline__ float hadd(ull v) { float2 t = upk(v); return t.x + t.y; }

// ---------------------------------------------------------------------------
// Fused actor MLP head: relu(h)->64->relu->64->relu->1.
// h passed as 32 packed registers (NO shared memory).
// Same arithmetic order as the SMEM version (bit-identical results).
// ---------------------------------------------------------------------------
__device__ __forceinline__ float mlp_head_reg(const float* __restrict__ sW1,
                                              const float* __restrict__ sW2T,
                                              const float* __restrict__ sb1,
                                              const float* __restrict__ sb2,
                                              const float* __restrict__ sW3,
                                              float b3v,
                                              const ull* __restrict__ h /* 32 regs */)
{
    ull acc2[32];
    const ull* sb2u = (const ull*)sb2;
#pragma unroll
    for (int jp = 0; jp < 32; jp++) acc2[jp] = sb2u[jp];

#pragma unroll 1
    for (int gb = 0; gb < 8; gb++) {
        ull a1p[8];
#pragma unroll
        for (int j = 0; j < 8; j++) a1p[j] = 0ULL;
#pragma unroll
        for (int kp = 0; kp < 32; kp += 2) {
            float2 va = upk(h[kp]);
            float2 vb = upk(h[kp + 1]);
            ull vva = pk(fmaxf(va.x, 0.0f), fmaxf(va.y, 0.0f));
            ull vvb = pk(fmaxf(vb.x, 0.0f), fmaxf(vb.y, 0.0f));
#pragma unroll
            for (int j = 0; j < 8; j++) {
                ulonglong2 w = ((const ulonglong2*)(sW1 + (gb * 8 + j) * HH))[kp >> 1];
                a1p[j] = ffma2(w.x, vva, a1p[j]);
                a1p[j] = ffma2(w.y, vvb, a1p[j]);
            }
        }
        float a1[8];
#pragma unroll
        for (int j = 0; j < 8; j++) a1[j] = fmaxf(hadd(a1p[j]) + sb1[gb * 8 + j], 0.0f);
#pragma unroll
        for (int kk = 0; kk < 8; kk++) {
            ull s = pk(a1[kk], a1[kk]);
            const ulonglong2* w2 = (const ulonglong2*)(sW2T + (gb * 8 + kk) * HH);
#pragma unroll
            for (int jq = 0; jq < 16; jq++) {
                ulonglong2 w = w2[jq];
                acc2[2 * jq]     = ffma2(w.x, s, acc2[2 * jq]);
                acc2[2 * jq + 1] = ffma2(w.y, s, acc2[2 * jq + 1]);
            }
        }
    }
    float acc = b3v;
#pragma unroll
    for (int jp = 0; jp < 32; jp++) {
        float2 a = upk(acc2[jp]);
        acc = fmaf(sW3[2 * jp],     fmaxf(a.x, 0.0f), acc);
        acc = fmaf(sW3[2 * jp + 1], fmaxf(a.y, 0.0f), acc);
    }
    return 3.0f * (fsig(acc) - 0.5f);
}

// ---------------------------------------------------------------------------
// Actor: one CTA per (zone n, 256-batch tile). Thread = one batch row.
// h lives ENTIRELY in registers (hA/hB packed ull[32]); SMEM holds weights only.
// t=0 skips the Whh GEMM (h0 == 0, bit-identical).
// ---------------------------------------------------------------------------
__global__ __launch_bounds__(ATH, 1)
void actor_kernel(const float* __restrict__ x,
                  const float* __restrict__ Wih, const float* __restrict__ Whh,
                  const float* __restrict__ bih, const float* __restrict__ bhh,
                  const float* __restrict__ W1,  const float* __restrict__ b1,
                  const float* __restrict__ W2,  const float* __restrict__ b2,
                  const float* __restrict__ W3,  const float* __restrict__ b3,
                  float* __restrict__ out)
{
    extern __shared__ float sm[];
    float* sWhh = sm;                   // 12288  [g][k] row-major
    float* sW1  = sWhh + G3 * HH;       // 4096   [g][k]
    float* sW2T = sW1 + HH * HH;        // 4096   [k][j] transposed
    float* sWih = sW2T + HH * HH;       // 1152   [g][s]
    float* sbih = sWih + G3 * SS;       // 192
    float* sbhh = sbih + G3;            // 192
    float* sb1  = sbhh + G3;            // 64
    float* sb2  = sb1 + HH;             // 64
    float* sW3  = sb2 + HH;             // 64
    float* sb3  = sW3 + HH;             // 4 (1 used)

    const int n   = blockIdx.y;
    const int tid = threadIdx.x;
    const int b   = blockIdx.x * ATH + tid;

    for (int i = tid; i < G3 * HH; i += ATH) sWhh[i] = Whh[n * G3 * HH + i];
    for (int i = tid; i < HH * HH; i += ATH) sW1[i]  = W1[n * HH * HH + i];
    for (int i = tid; i < HH * HH; i += ATH) { int j = i >> 6, k = i & 63; sW2T[k * HH + j] = W2[n * HH * HH + i]; }
    for (int i = tid; i < G3 * SS; i += ATH) sWih[i] = Wih[n * G3 * SS + i];
    if (tid < G3) { sbih[tid] = bih[n * G3 + tid]; sbhh[tid] = bhh[n * G3 + tid]; }
    if (tid < HH) { sb1[tid] = b1[n * HH + tid]; sb2[tid] = b2[n * HH + tid]; sW3[tid] = W3[n * HH + tid]; }
    if (tid == 0) sb3[0] = b3[n];
    __syncthreads();

    ull hA[32];   // h after t=0 (packed gate pairs)

    // ======================= t = 0 (h0 == 0: no Whh work) =======================
    {
        const float* xr = x + ((size_t)(b * TT + 0) * NZ + n) * SS;
        float2 x0 = *(const float2*)xr, x1 = *(const float2*)(xr + 2), x2 = *(const float2*)(xr + 4);
        ull xp0 = pk(x0.x, x0.y), xp1 = pk(x1.x, x1.y), xp2 = pk(x2.x, x2.y);

#pragma unroll
        for (int gp = 0; gp < 32; gp++) {
            const int g0 = gp * 2, g1 = g0 + 1;
            const ull* wr0 = (const ull*)(sWih + g0 * SS);
            const ull* wz0 = (const ull*)(sWih + (HH + g0) * SS);
            const ull* wn0 = (const ull*)(sWih + (2 * HH + g0) * SS);
            const ull* wr1 = (const ull*)(sWih + g1 * SS);
            const ull* wz1 = (const ull*)(sWih + (HH + g1) * SS);
            const ull* wn1 = (const ull*)(sWih + (2 * HH + g1) * SS);
            ull aR0 = ffma2(wr0[0], xp0, ffma2(wr0[1], xp1, ffma2(wr0[2], xp2, 0ULL)));
            ull aZ0 = ffma2(wz0[0], xp0, ffma2(wz0[1], xp1, ffma2(wz0[2], xp2, 0ULL)));
            ull aN0 = ffma2(wn0[0], xp0, ffma2(wn0[1], xp1, ffma2(wn0[2], xp2, 0ULL)));
            ull aR1 = ffma2(wr1[0], xp0, ffma2(wr1[1], xp1, ffma2(wr1[2], xp2, 0ULL)));
            ull aZ1 = ffma2(wz1[0], xp0, ffma2(wz1[1], xp1, ffma2(wz1[2], xp2, 0ULL)));
            ull aN1 = ffma2(wn1[0], xp0, ffma2(wn1[1], xp1, ffma2(wn1[2], xp2, 0ULL)));

            float ar0  = sbih[g0] + sbhh[g0] + hadd(aR0);
            float az0  = sbih[HH + g0] + sbhh[HH + g0] + hadd(aZ0);
            float anx0 = sbih[2 * HH + g0] + hadd(aN0);
            float anh0 = sbhh[2 * HH + g0];
            float ar1  = sbih[g1] + sbhh[g1] + hadd(aR1);
            float az1  = sbih[HH + g1] + sbhh[HH + g1] + hadd(aZ1);
            float anx1 = sbih[2 * HH + g1] + hadd(aN1);
            float anh1 = sbhh[2 * HH + g1];

            float r0 = fsig(ar0), z0 = fsig(az0);
            float nn0 = ftanh(fmaf(r0, anh0, anx0));
            float r1 = fsig(ar1), z1 = fsig(az1);
            float nn1 = ftanh(fmaf(r1, anh1, anx1));
            hA[gp] = pk((1.0f - z0) * nn0, (1.0f - z1) * nn1);   // h_new = (1-z)*n (+z*0)
        }

        float act = mlp_head_reg(sW1, sW2T, sb1, sb2, sW3, sb3[0], hA);
        int F = n * (BB * TT) + b * TT + 0;
        g_Aflat[F] = act;
        if (((F / 100) & 1) == 1) out[(F / 200) * 100 + (F % 100)] = act;
    }

    // ======================= t = 1 (full GRU step) =======================
    {
        ull hB[32];

        const float* xr = x + ((size_t)(b * TT + 1) * NZ + n) * SS;
        float2 x0 = *(const float2*)xr, x1 = *(const float2*)(xr + 2), x2 = *(const float2*)(xr + 4);
        ull xp0 = pk(x0.x, x0.y), xp1 = pk(x1.x, x1.y), xp2 = pk(x2.x, x2.y);

#pragma unroll
        for (int gp = 0; gp < 32; gp++) {
            const int g0 = gp * 2, g1 = g0 + 1;
            const ull* wr0 = (const ull*)(sWih + g0 * SS);
            const ull* wz0 = (const ull*)(sWih + (HH + g0) * SS);
            const ull* wn0 = (const ull*)(sWih + (2 * HH + g0) * SS);
            const ull* wr1 = (const ull*)(sWih + g1 * SS);
            const ull* wz1 = (const ull*)(sWih + (HH + g1) * SS);
            const ull* wn1 = (const ull*)(sWih + (2 * HH + g1) * SS);
            ull aR0 = ffma2(wr0[0], xp0, ffma2(wr0[1], xp1, ffma2(wr0[2], xp2, 0ULL)));
            ull aZ0 = ffma2(wz0[0], xp0, ffma2(wz0[1], xp1, ffma2(wz0[2], xp2, 0ULL)));
            ull aN0 = ffma2(wn0[0], xp0, ffma2(wn0[1], xp1, ffma2(wn0[2], xp2, 0ULL)));
            ull aR1 = ffma2(wr1[0], xp0, ffma2(wr1[1], xp1, ffma2(wr1[2], xp2, 0ULL)));
            ull aZ1 = ffma2(wz1[0], xp0, ffma2(wz1[1], xp1, ffma2(wz1[2], xp2, 0ULL)));
            ull aN1 = ffma2(wn1[0], xp0, ffma2(wn1[1], xp1, ffma2(wn1[2], xp2, 0ULL)));
            float arx0 = hadd(aR0), azx0 = hadd(aZ0), anx0s = hadd(aN0);
            float arx1 = hadd(aR1), azx1 = hadd(aZ1), anx1s = hadd(aN1);

            // 2-way split accumulator chains; h_old read from hA registers.
            ull hR0a = 0ULL, hZ0a = 0ULL, hN0a = 0ULL;
            ull hR1a = 0ULL, hZ1a = 0ULL, hN1a = 0ULL;
            ull hR0b = 0ULL, hZ0b = 0ULL, hN0b = 0ULL;
            ull hR1b = 0ULL, hZ1b = 0ULL, hN1b = 0ULL;
            const ulonglong2* wR0 = (const ulonglong2*)(sWhh + g0 * HH);
            const ulonglong2* wZ0 = (const ulonglong2*)(sWhh + (HH + g0) * HH);
            const ulonglong2* wN0 = (const ulonglong2*)(sWhh + (2 * HH + g0) * HH);
            const ulonglong2* wR1 = (const ulonglong2*)(sWhh + g1 * HH);
            const ulonglong2* wZ1 = (const ulonglong2*)(sWhh + (HH + g1) * HH);
            const ulonglong2* wN1 = (const ulonglong2*)(sWhh + (2 * HH + g1) * HH);
#pragma unroll
            for (int q = 0; q < 8; q++) {
                ull ha = hA[2 * q], hb = hA[2 * q + 1];
                ulonglong2 a0 = wR0[q], c0 = wZ0[q], d0 = wN0[q];
                hR0a = ffma2(a0.x, ha, hR0a); hR0a = ffma2(a0.y, hb, hR0a);
                hZ0a = ffma2(c0.x, ha, hZ0a); hZ0a = ffma2(c0.y, hb, hZ0a);
                hN0a = ffma2(d0.x, ha, hN0a); hN0a = ffma2(d0.y, hb, hN0a);
                ulonglong2 a1 = wR1[q], c1 = wZ1[q], d1 = wN1[q];
                hR1a = ffma2(a1.x, ha, hR1a); hR1a = ffma2(a1.y, hb, hR1a);
                hZ1a = ffma2(c1.x, ha, hZ1a); hZ1a = ffma2(c1.y, hb, hZ1a);
                hN1a = ffma2(d1.x, ha, hN1a); hN1a = ffma2(d1.y, hb, hN1a);
            }
#pragma unroll
            for (int q = 8; q < 16; q++) {
                ull ha = hA[2 * q], hb = hA[2 * q + 1];
                ulonglong2 a0 = wR0[q], c0 = wZ0[q], d0 = wN0[q];
                hR0b = ffma2(a0.x, ha, hR0b); hR0b = ffma2(a0.y, hb, hR0b);
                hZ0b = ffma2(c0.x, ha, hZ0b); hZ0b = ffma2(c0.y, hb, hZ0b);
                hN0b = ffma2(d0.x, ha, hN0b); hN0b = ffma2(d0.y, hb, hN0b);
                ulonglong2 a1 = wR1[q], c1 = wZ1[q], d1 = wN1[q];
                hR1b = ffma2(a1.x, ha, hR1b); hR1b = ffma2(a1.y, hb, hR1b);
                hZ1b = ffma2(c1.x, ha, hZ1b); hZ1b = ffma2(c1.y, hb, hZ1b);
                hN1b = ffma2(d1.x, ha, hN1b); hN1b = ffma2(d1.y, hb, hN1b);
            }
            ull hR0 = fadd2(hR0a, hR0b), hZ0 = fadd2(hZ0a, hZ0b), hN0 = fadd2(hN0a, hN0b);
            ull hR1 = fadd2(hR1a, hR1b), hZ1 = fadd2(hZ1a, hZ1b), hN1 = fadd2(hN1a, hN1b);

            float ar0  = sbih[g0] + sbhh[g0] + arx0 + hadd(hR0);
            float az0  = sbih[HH + g0] + sbhh[HH + g0] + azx0 + hadd(hZ0);
            float anx0 = sbih[2 * HH + g0] + anx0s;
            float anh0 = sbhh[2 * HH + g0] + hadd(hN0);
            float ar1  = sbih[g1] + sbhh[g1] + arx1 + hadd(hR1);
            float az1  = sbih[HH + g1] + sbhh[HH + g1] + azx1 + hadd(hZ1);
            float anx1 = sbih[2 * HH + g1] + anx1s;
            float anh1 = sbhh[2 * HH + g1] + hadd(hN1);

            float r0 = fsig(ar0), z0 = fsig(az0);
            float nn0 = ftanh(fmaf(r0, anh0, anx0));
            float r1 = fsig(ar1), z1 = fsig(az1);
            float nn1 = ftanh(fmaf(r1, anh1, anx1));

            float2 holdp = upk(hA[gp]);    // h_old from registers
            float hn0 = fmaf(z0, holdp.x, (1.0f - z0) * nn0);
            float hn1 = fmaf(z1, holdp.y, (1.0f - z1) * nn1);
            hB[gp] = pk(hn0, hn1);
        }

        float act = mlp_head_reg(sW1, sW2T, sb1, sb2, sW3, sb3[0], hB);
        int F = n * (BB * TT) + b * TT + 1;
        g_Aflat[F] = act;
        if (((F / 100) & 1) == 1) out[(F / 200) * 100 + (F % 100)] = act;
    }
}

// ---------------------------------------------------------------------------
// Critic + LocalizedModule (combined, R11 known-good): warp-per-batch-row,
// 16 warps/CTA, grid 128. Padded SMEM strides kill transpose write conflicts.
// ---------------------------------------------------------------------------
__global__ __launch_bounds__(32 * CW, 1)
void critic_kernel(const float* __restrict__ x,
                   const float* __restrict__ lmW1, const float* __restrict__ lmb1,
                   const float* __restrict__ lmW2, const float* __restrict__ lmb2,
                   const float* __restrict__ lmW3, const float* __restrict__ lmb3,
                   const float* __restrict__ scWih, const float* __restrict__ scWhh,
                   const float* __restrict__ scbih, const float* __restrict__ scbhh,
                   const float* __restrict__ scW1,  const float* __restrict__ scb1,
                   const float* __restrict__ scW2,  const float* __restrict__ scb2,
                   const float* __restrict__ scW3,  const float* __restrict__ scb3,
                   float* __restrict__ out)
{
    extern __shared__ float sm[];
    float* sWih = sm;                     // [i][g]  NBF*G3P
    float* sWhh = sWih + NBF * G3P;       // [k][g]  HH*G3P
    float* sW1  = sWhh + HH * G3P;        // [k][j]  HH*HHP
    float* sW2  = sW1 + HH * HHP;         // [k][j]  HH*HHP
    float* sW3  = sW2 + HH * HHP;         // 64
    float* sbih = sW3 + HH;               // 192
    float* sbhh = sbih + G3;              // 192
    float* sb1  = sbhh + G3;              // 64
    float* sb2  = sb1 + HH;               // 64
    float* sb3c = sb2 + HH;               // 4 (1 used)
    float* sLW1 = sb3c + 4;               // [i][j]  NBF*LMP
    float* sLW2 = sLW1 + NBF * LMP;       // [k][j]  LMH*LMP
    float* sLW3 = sLW2 + LMH * LMP;       // 128
    float* sLb1 = sLW3 + LMH;             // 128
    float* sLb2 = sLb1 + LMH;             // 128
    float* sLb3 = sLb2 + LMH;             // 4 (1 used)
    float* sXi  = sLb3 + 4;               // CW * 2*35
    float* sH   = sXi + CW * 2 * NBF;     // CW * 64
    float* sBuf = sH + CW * HH;           // CW * 128

    const int tid = threadIdx.x;
    const int NTH = 32 * CW;

    for (int idx = tid; idx < G3 * NBF; idx += NTH) { int g = idx / NBF, i = idx % NBF; sWih[i * G3P + g] = scWih[idx]; }
    for (int idx = tid; idx < G3 * HH;  idx += NTH) { int g = idx / HH,  k = idx % HH;  sWhh[k * G3P + g] = scWhh[idx]; }
    for (int idx = tid; idx < HH * HH;  idx += NTH) { int j = idx / HH,  k = idx % HH;  sW1[k * HHP + j]  = scW1[idx]; }
    for (int idx = tid; idx < HH * HH;  idx += NTH) { int j = idx / HH,  k = idx % HH;  sW2[k * HHP + j]  = scW2[idx]; }
    for (int idx = tid; idx < LMH * NBF; idx += NTH) { int j = idx / NBF, i = idx % NBF; sLW1[i * LMP + j] = lmW1[idx]; }
    for (int idx = tid; idx < LMH * LMH; idx += NTH) { int j = idx / LMH, k = idx % LMH; sLW2[k * LMP + j] = lmW2[idx]; }
    if (tid < G3)  { sbih[tid] = scbih[tid]; sbhh[tid] = scbhh[tid]; }
    if (tid < HH)  { sW3[tid] = scW3[tid]; sb1[tid] = scb1[tid]; sb2[tid] = scb2[tid]; }
    if (tid < LMH) { sLW3[tid] = lmW3[tid]; sLb1[tid] = lmb1[tid]; sLb2[tid] = lmb2[tid]; }
    if (tid == 0)  { sb3c[0] = scb3[0]; sLb3[0] = lmb3[0]; }
    __syncthreads();

    const int w = tid >> 5, l = tid & 31;
    const int b = blockIdx.x * CW + w;
    float* xi = sXi + w * (2 * NBF);
    float* hs = sH + w * HH;
    float* bf = sBuf + w * LMH;

    // Build xi[t][35]: [xc99(7), xc89(7), zeros(7), zeros(7), xc98(7)]
    for (int i = l; i < NBF; i += 32) {
#pragma unroll
        for (int t = 0; t < TT; t++) {
            float v;
            if (i < 6)        v = x[((b * TT + t) * NZ + 99) * SS + i];
            else if (i == 6)  v = g_Aflat[200 * b + 100 * t + 99];
            else if (i < 13)  v = x[((b * TT + t) * NZ + 89) * SS + (i - 7)];
            else if (i == 13) v = g_Aflat[200 * b + 100 * t + 89];
            else if (i < 28)  v = 0.0f;
            else if (i < 34)  v = x[((b * TT + t) * NZ + 98) * SS + (i - 28)];
            else              v = g_Aflat[200 * b + 100 * t + 98];
            xi[t * NBF + i] = v;
        }
    }
    hs[l] = 0.0f; hs[l + 32] = 0.0f;
    __syncwarp();

    const int u0 = l, u1 = l + 32;

    // --- SubCritic GRU, 2 steps. Lane owns hidden units u0, u1. ---
    for (int t = 0; t < TT; t++) {
        float ar0 = sbih[u0] + sbhh[u0], az0 = sbih[64 + u0] + sbhh[64 + u0];
        float an0 = sbih[128 + u0],      ah0 = sbhh[128 + u0];
        float ar1 = sbih[u1] + sbhh[u1], az1 = sbih[64 + u1] + sbhh[64 + u1];
        float an1 = sbih[128 + u1],      ah1 = sbhh[128 + u1];
        const float* xit = xi + t * NBF;
#pragma unroll
        for (int i = 0; i < NBF; i++) {
            float xv = xit[i];
            const float* wc = sWih + i * G3P;
            ar0 = fmaf(wc[u0],      xv, ar0); az0 = fmaf(wc[64 + u0],  xv, az0); an0 = fmaf(wc[128 + u0], xv, an0);
            ar1 = fmaf(wc[u1],      xv, ar1); az1 = fmaf(wc[64 + u1],  xv, az1); an1 = fmaf(wc[128 + u1], xv, an1);
        }
        // n-gate recurrent term accumulates into ah: n = tanh(xn + r*(Whh_n h + bhh_n))
#pragma unroll
        for (int k = 0; k < HH; k++) {
            float hk = hs[k];
            const float* wc = sWhh + k * G3P;
            ar0 = fmaf(wc[u0],      hk, ar0); az0 = fmaf(wc[64 + u0],  hk, az0); ah0 = fmaf(wc[128 + u0], hk, ah0);
            ar1 = fmaf(wc[u1],      hk, ar1); az1 = fmaf(wc[64 + u1],  hk, az1); ah1 = fmaf(wc[128 + u1], hk, ah1);
        }
        float r0 = fsig(ar0), z0 = fsig(az0), n0 = ftanh(fmaf(r0, ah0, an0));
        float r1 = fsig(ar1), z1 = fsig(az1), n1 = ftanh(fmaf(r1, ah1, an1));
        float hn0 = (1.0f - z0) * n0 + z0 * hs[u0];
        float hn1 = (1.0f - z1) * n1 + z1 * hs[u1];
        __syncwarp();
        hs[u0] = hn0; hs[u1] = hn1;
        __syncwarp();
    }

    // --- q MLP: relu(h) -> 64 -> 64 -> 1 ---
    float a0 = sb1[u0], a1 = sb1[u1];
#pragma unroll
    for (int k = 0; k < HH; k++) {
        float ck = fmaxf(hs[k], 0.0f);
        a0 = fmaf(sW1[k * HHP + u0], ck, a0);
        a1 = fmaf(sW1[k * HHP + u1], ck, a1);
    }
    bf[u0] = fmaxf(a0, 0.0f); bf[u1] = fmaxf(a1, 0.0f);
    __syncwarp();
    a0 = sb2[u0]; a1 = sb2[u1];
#pragma unroll
    for (int k = 0; k < HH; k++) {
        float ck = bf[k];
        a0 = fmaf(sW2[k * HHP + u0], ck, a0);
        a1 = fmaf(sW2[k * HHP + u1], ck, a1);
    }
    float part = sW3[u0] * fmaxf(a0, 0.0f) + sW3[u1] * fmaxf(a1, 0.0f);
#pragma unroll
    for (int off = 16; off > 0; off >>= 1) part += __shfl_xor_sync(0xffffffffu, part, off);
    float q = part + sb3c[0];
    __syncwarp();   // all bf reads done before LM reuses bf

    // --- LocalizedModule on xi[t=1]: 35 -> 128 -> 128 -> 1. Lane owns 4 units. ---
    const int v0 = l, v1 = l + 32, v2 = l + 64, v3 = l + 96;
    float f0 = sLb1[v0], f1 = sLb1[v1], f2 = sLb1[v2], f3 = sLb1[v3];
    const float* xit = xi + NBF;
#pragma unroll
    for (int i = 0; i < NBF; i++) {
        float xv = xit[i];
        const float* wc = sLW1 + i * LMP;
        f0 = fmaf(wc[v0], xv, f0); f1 = fmaf(wc[v1], xv, f1);
        f2 = fmaf(wc[v2], xv, f2); f3 = fmaf(wc[v3], xv, f3);
    }
    bf[v0] = fmaxf(f0, 0.0f); bf[v1] = fmaxf(f1, 0.0f);
    bf[v2] = fmaxf(f2, 0.0f); bf[v3] = fmaxf(f3, 0.0f);
    __syncwarp();
    f0 = sLb2[v0]; f1 = sLb2[v1]; f2 = sLb2[v2]; f3 = sLb2[v3];
#pragma unroll 8
    for (int k = 0; k < LMH; k++) {
        float ck = bf[k];
        const float* wc = sLW2 + k * LMP;
        f0 = fmaf(wc[v0], ck, f0); f1 = fmaf(wc[v1], ck, f1);
        f2 = fmaf(wc[v2], ck, f2); f3 = fmaf(wc[v3], ck, f3);
    }
    float pf = sLW3[v0] * fmaxf(f0, 0.0f) + sLW3[v1] * fmaxf(f1, 0.0f)
             + sLW3[v2] * fmaxf(f2, 0.0f) + sLW3[v3] * fmaxf(f3, 0.0f);
#pragma unroll
    for (int off = 16; off > 0; off >>= 1) pf += __shfl_xor_sync(0xffffffffu, pf, off);

    if (l == 0) out[BB * NZ + b] = (pf + sLb3[0]) + q;
}

// ---------------------------------------------------------------------------
extern "C" void kernel_launch(void* const* d_in, const int* in_sizes, int n_in,
                              void* d_out, int out_size)
{
    const float* x      = (const float*)d_in[0];
    const float* a_Wih  = (const float*)d_in[1];
    const float* a_Whh  = (const float*)d_in[2];
    const float* a_bih  = (const float*)d_in[3];
    const float* a_bhh  = (const float*)d_in[4];
    const float* a_W1   = (const float*)d_in[5];
    const float* a_b1   = (const float*)d_in[6];
    const float* a_W2   = (const float*)d_in[7];
    const float* a_b2   = (const float*)d_in[8];
    const float* a_W3   = (const float*)d_in[9];
    const float* a_b3   = (const float*)d_in[10];
    const float* lm_W1  = (const float*)d_in[11];
    const float* lm_b1  = (const float*)d_in[12];
    const float* lm_W2  = (const float*)d_in[13];
    const float* lm_b2  = (const float*)d_in[14];
    const float* lm_W3  = (const float*)d_in[15];
    const float* lm_b3  = (const float*)d_in[16];
    const float* sc_Wih = (const float*)d_in[17];
    const float* sc_Whh = (const float*)d_in[18];
    const float* sc_bih = (const float*)d_in[19];
    const float* sc_bhh = (const float*)d_in[20];
    const float* sc_W1  = (const float*)d_in[21];
    const float* sc_b1  = (const float*)d_in[22];
    const float* sc_W2  = (const float*)d_in[23];
    const float* sc_b2  = (const float*)d_in[24];
    const float* sc_W3  = (const float*)d_in[25];
    const float* sc_b3  = (const float*)d_in[26];
    float* out = (float*)d_out;

    // Actor SMEM: weights only (22212 floats ~ 87KB); h lives in registers.
    constexpr size_t SMA = (size_t)(12288 + 4096 + 4096 + 1152 + 192 + 192 + 64 + 64 + 64 + 4) * sizeof(float);
    // Critic SMEM (padded strides, CW=16)
    constexpr size_t SMC = (size_t)(NBF*G3P + HH*G3P + HH*HHP + HH*HHP + HH + G3 + G3 + HH + HH + 4
                                    + NBF*LMP + LMH*LMP + LMH + LMH + LMH + 4
                                    + CW * (2*NBF) + CW * HH + CW * LMH) * sizeof(float);

    cudaFuncSetAttribute(actor_kernel,  cudaFuncAttributeMaxDynamicSharedMemorySize, (int)SMA);
    cudaFuncSetAttribute(critic_kernel, cudaFuncAttributeMaxDynamicSharedMemorySize, (int)SMC);

    actor_kernel<<<dim3(BB / ATH, NZ), ATH, SMA>>>(
        x, a_Wih, a_Whh, a_bih, a_bhh, a_W1, a_b1, a_W2, a_b2, a_W3, a_b3, out);

    critic_kernel<<<BB / CW, 32 * CW, SMC>>>(
        x, lm_W1, lm_b1, lm_W2, lm_b2, lm_W3, lm_b3,
        sc_Wih, sc_Whh, sc_bih, sc_bhh, sc_W1, sc_b1, sc_W2, sc_b2, sc_W3, sc_b3,
        out);
}

// round 15
// speedup vs baseline: 1.2587x; 1.2587x over previous
#include <cuda_runtime.h>

// Problem constants
#define BB  2048   // batch
#define TT  2      // timesteps
#define NZ  100    // zones
#define SS  6      // state
#define HH  64     // hidden (actor + critic)
#define G3  192    // 3*H gate rows
#define NBF 35     // neighbor feature size
#define LMH 128    // localized module hidden
#define ATH 512    // actor threads per CTA == batch tile
#define CW  16     // critic warps per CTA
// padded strides (critic SMEM, kill 32-way write conflicts)
#define G3P 193
#define HHP 65
#define LMP 129

typedef unsigned long long ull;

// Actor output scratch, layout Aflat[n*(B*T) + b*T + t]  (== flatten of [N,B,T])
//   p[b,t,n] = Aflat[200*b + 100*t + n]
// The reshape scramble makes EVERY Aflat entry live in output 0 (R8 lesson).
// Fused p-output inverse map: element F=4096n+2b+t is out_p[F/200, F%100]
// iff (F/100) is odd.
__device__ float g_Aflat[NZ * BB * TT];

__device__ __forceinline__ float fsig(float x) {
    return __fdividef(1.0f, 1.0f + __expf(-x));
}
__device__ __forceinline__ float ftanh(float x) {
    return 1.0f - __fdividef(2.0f, __expf(2.0f * x) + 1.0f);
}
// packed f32x2 helpers (Blackwell)
__device__ __forceinline__ ull pk(float a, float b) {
    ull r; asm("mov.b64 %0,{%1,%2};" : "=l"(r) : "f"(a), "f"(b)); return r;
}
__device__ __forceinline__ float2 upk(ull v) {
    float2 r; asm("mov.b64 {%0,%1},%2;" : "=f"(r.x), "=f"(r.y) : "l"(v)); return r;
}
__device__ __forceinline__ ull ffma2(ull a, ull b, ull c) {   // a*b+c, 2 lanes
    ull d; asm("fma.rn.f32x2 %0,%1,%2,%3;" : "=l"(d) : "l"(a), "l"(b), "l"(c)); return d;
}
__device__ __forceinline__ ull fadd2(ull a, ull b) {
    ull d; asm("add.rn.f32x2 %0,%1,%2;" : "=l"(d) : "l"(a), "l"(b)); return d;
}
__device__ __forceinline__ float hadd(ull v) { float2 t = upk(v); return t.x + t.y; }

// ---------------------------------------------------------------------------
// Fused actor MLP head: relu(h)->64->relu->64->relu->1, h packed in scrA.
// Layer1 in 4 blocks of 16 gates (was 8x8): h re-read 4x instead of 8x.
// Per-output arithmetic order unchanged (k ascending) => bit-identical.
// ---------------------------------------------------------------------------
__device__ __forceinline__ float mlp_head(const float* __restrict__ sW1,
                                          const float* __restrict__ sW2T,
                                          const float* __restrict__ sb1,
                                          const float* __restrict__ sb2,
                                          const float* __restrict__ sW3,
                                          float b3v,
                                          const ull* __restrict__ scrAu,
                                          int tid)
{
    ull acc2[32];
    const ull* sb2u = (const ull*)sb2;
#pragma unroll
    for (int jp = 0; jp < 32; jp++) acc2[jp] = sb2u[jp];

    for (int gb = 0; gb < 4; gb++) {
        ull a1p[16];
#pragma unroll
        for (int j = 0; j < 16; j++) a1p[j] = 0ULL;
#pragma unroll 4
        for (int kp = 0; kp < 32; kp += 2) {
            float2 va = upk(scrAu[kp * ATH + tid]);
            float2 vb = upk(scrAu[(kp + 1) * ATH + tid]);
            ull vva = pk(fmaxf(va.x, 0.0f), fmaxf(va.y, 0.0f));
            ull vvb = pk(fmaxf(vb.x, 0.0f), fmaxf(vb.y, 0.0f));
#pragma unroll
            for (int j = 0; j < 16; j++) {
                ulonglong2 w = ((const ulonglong2*)(sW1 + (gb * 16 + j) * HH))[kp >> 1];
                a1p[j] = ffma2(w.x, vva, a1p[j]);
                a1p[j] = ffma2(w.y, vvb, a1p[j]);
            }
        }
        float a1[16];
#pragma unroll
        for (int j = 0; j < 16; j++) a1[j] = fmaxf(hadd(a1p[j]) + sb1[gb * 16 + j], 0.0f);
#pragma unroll
        for (int kk = 0; kk < 16; kk++) {
            ull s = pk(a1[kk], a1[kk]);
            const ulonglong2* w2 = (const ulonglong2*)(sW2T + (gb * 16 + kk) * HH);
#pragma unroll
            for (int jq = 0; jq < 16; jq++) {
                ulonglong2 w = w2[jq];
                acc2[2 * jq]     = ffma2(w.x, s, acc2[2 * jq]);
                acc2[2 * jq + 1] = ffma2(w.y, s, acc2[2 * jq + 1]);
            }
        }
    }
    float acc = b3v;
#pragma unroll
    for (int jp = 0; jp < 32; jp++) {
        float2 a = upk(acc2[jp]);
        acc = fmaf(sW3[2 * jp],     fmaxf(a.x, 0.0f), acc);
        acc = fmaf(sW3[2 * jp + 1], fmaxf(a.y, 0.0f), acc);
    }
    return 3.0f * (fsig(acc) - 0.5f);
}

// ---------------------------------------------------------------------------
// Actor: one CTA per (zone n, 512-batch tile). Thread = one batch row.
// All weights in SMEM; h scratch packed float2[32][512] (in-place update).
// t=0 skips the Whh GEMM entirely (h0 == 0, bit-identical).
// p-output (scramble gather) fused: no separate pcopy kernel.
// ---------------------------------------------------------------------------
__global__ __launch_bounds__(ATH, 1)
void actor_kernel(const float* __restrict__ x,
                  const float* __restrict__ Wih, const float* __restrict__ Whh,
                  const float* __restrict__ bih, const float* __restrict__ bhh,
                  const float* __restrict__ W1,  const float* __restrict__ b1,
                  const float* __restrict__ W2,  const float* __restrict__ b2,
                  const float* __restrict__ W3,  const float* __restrict__ b3,
                  float* __restrict__ out)
{
    extern __shared__ float sm[];
    float* sWhh = sm;                   // 12288  [g][k] row-major
    float* sW1  = sWhh + G3 * HH;       // 4096   [g][k]
    float* sW2T = sW1 + HH * HH;        // 4096   [k][j] transposed
    float* sWih = sW2T + HH * HH;       // 1152   [g][s]
    float* sbih = sWih + G3 * SS;       // 192
    float* sbhh = sbih + G3;            // 192
    float* sb1  = sbhh + G3;            // 64
    float* sb2  = sb1 + HH;             // 64
    float* sW3  = sb2 + HH;             // 64
    float* sb3  = sW3 + HH;             // 4 (1 used)
    float* scrAf = sb3 + 4;             // 32*512 float2 (packed h)
    ull*   scrAu = (ull*)scrAf;

    const int n   = blockIdx.y;
    const int tid = threadIdx.x;
    const int b   = blockIdx.x * ATH + tid;

    for (int i = tid; i < G3 * HH; i += ATH) sWhh[i] = Whh[n * G3 * HH + i];
    for (int i = tid; i < HH * HH; i += ATH) sW1[i]  = W1[n * HH * HH + i];
    for (int i = tid; i < HH * HH; i += ATH) { int j = i >> 6, k = i & 63; sW2T[k * HH + j] = W2[n * HH * HH + i]; }
    for (int i = tid; i < G3 * SS; i += ATH) sWih[i] = Wih[n * G3 * SS + i];
    if (tid < G3) { sbih[tid] = bih[n * G3 + tid]; sbhh[tid] = bhh[n * G3 + tid]; }
    if (tid < HH) { sb1[tid] = b1[n * HH + tid]; sb2[tid] = b2[n * HH + tid]; sW3[tid] = W3[n * HH + tid]; }
    if (tid == 0) sb3[0] = b3[n];
    __syncthreads();

    // ======================= t = 0 (h0 == 0: no Whh work) =======================
    {
        const float* xr = x + ((size_t)(b * TT + 0) * NZ + n) * SS;
        float2 x0 = *(const float2*)xr, x1 = *(const float2*)(xr + 2), x2 = *(const float2*)(xr + 4);
        ull xp0 = pk(x0.x, x0.y), xp1 = pk(x1.x, x1.y), xp2 = pk(x2.x, x2.y);

#pragma unroll 2
        for (int gp = 0; gp < 32; gp++) {
            const int g0 = gp * 2, g1 = g0 + 1;
            const ull* wr0 = (const ull*)(sWih + g0 * SS);
            const ull* wz0 = (const ull*)(sWih + (HH + g0) * SS);
            const ull* wn0 = (const ull*)(sWih + (2 * HH + g0) * SS);
            const ull* wr1 = (const ull*)(sWih + g1 * SS);
            const ull* wz1 = (const ull*)(sWih + (HH + g1) * SS);
            const ull* wn1 = (const ull*)(sWih + (2 * HH + g1) * SS);
            ull aR0 = ffma2(wr0[0], xp0, ffma2(wr0[1], xp1, ffma2(wr0[2], xp2, 0ULL)));
            ull aZ0 = ffma2(wz0[0], xp0, ffma2(wz0[1], xp1, ffma2(wz0[2], xp2, 0ULL)));
            ull aN0 = ffma2(wn0[0], xp0, ffma2(wn0[1], xp1, ffma2(wn0[2], xp2, 0ULL)));
            ull aR1 = ffma2(wr1[0], xp0, ffma2(wr1[1], xp1, ffma2(wr1[2], xp2, 0ULL)));
            ull aZ1 = ffma2(wz1[0], xp0, ffma2(wz1[1], xp1, ffma2(wz1[2], xp2, 0ULL)));
            ull aN1 = ffma2(wn1[0], xp0, ffma2(wn1[1], xp1, ffma2(wn1[2], xp2, 0ULL)));

            float ar0  = sbih[g0] + sbhh[g0] + hadd(aR0);
            float az0  = sbih[HH + g0] + sbhh[HH + g0] + hadd(aZ0);
            float anx0 = sbih[2 * HH + g0] + hadd(aN0);
            float anh0 = sbhh[2 * HH + g0];
            float ar1  = sbih[g1] + sbhh[g1] + hadd(aR1);
            float az1  = sbih[HH + g1] + sbhh[HH + g1] + hadd(aZ1);
            float anx1 = sbih[2 * HH + g1] + hadd(aN1);
            float anh1 = sbhh[2 * HH + g1];

            float r0 = fsig(ar0), z0 = fsig(az0);
            float nn0 = ftanh(fmaf(r0, anh0, anx0));
            float r1 = fsig(ar1), z1 = fsig(az1);
            float nn1 = ftanh(fmaf(r1, anh1, anx1));
            scrAu[gp * ATH + tid] = pk((1.0f - z0) * nn0, (1.0f - z1) * nn1);
        }

        float act = mlp_head(sW1, sW2T, sb1, sb2, sW3, sb3[0], scrAu, tid);
        int F = n * (BB * TT) + b * TT + 0;
        g_Aflat[F] = act;
        if (((F / 100) & 1) == 1) out[(F / 200) * 100 + (F % 100)] = act;
    }

    // ======================= t = 1 (full GRU step) =======================
    {
        ull h2[32];
#pragma unroll
        for (int kp = 0; kp < 32; kp++) h2[kp] = scrAu[kp * ATH + tid];

        const float* xr = x + ((size_t)(b * TT + 1) * NZ + n) * SS;
        float2 x0 = *(const float2*)xr, x1 = *(const float2*)(xr + 2), x2 = *(const float2*)(xr + 4);
        ull xp0 = pk(x0.x, x0.y), xp1 = pk(x1.x, x1.y), xp2 = pk(x2.x, x2.y);

#pragma unroll 1
        for (int gp = 0; gp < 32; gp++) {
            const int g0 = gp * 2, g1 = g0 + 1;
            const ull* wr0 = (const ull*)(sWih + g0 * SS);
            const ull* wz0 = (const ull*)(sWih + (HH + g0) * SS);
            const ull* wn0 = (const ull*)(sWih + (2 * HH + g0) * SS);
            const ull* wr1 = (const ull*)(sWih + g1 * SS);
            const ull* wz1 = (const ull*)(sWih + (HH + g1) * SS);
            const ull* wn1 = (const ull*)(sWih + (2 * HH + g1) * SS);
            ull aR0 = ffma2(wr0[0], xp0, ffma2(wr0[1], xp1, ffma2(wr0[2], xp2, 0ULL)));
            ull aZ0 = ffma2(wz0[0], xp0, ffma2(wz0[1], xp1, ffma2(wz0[2], xp2, 0ULL)));
            ull aN0 = ffma2(wn0[0], xp0, ffma2(wn0[1], xp1, ffma2(wn0[2], xp2, 0ULL)));
            ull aR1 = ffma2(wr1[0], xp0, ffma2(wr1[1], xp1, ffma2(wr1[2], xp2, 0ULL)));
            ull aZ1 = ffma2(wz1[0], xp0, ffma2(wz1[1], xp1, ffma2(wz1[2], xp2, 0ULL)));
            ull aN1 = ffma2(wn1[0], xp0, ffma2(wn1[1], xp1, ffma2(wn1[2], xp2, 0ULL)));
            float arx0 = hadd(aR0), azx0 = hadd(aZ0), anx0s = hadd(aN0);
            float arx1 = hadd(aR1), azx1 = hadd(aZ1), anx1s = hadd(aN1);

            // 2-way split accumulator chains (halved dependency depth).
            ull hR0a = 0ULL, hZ0a = 0ULL, hN0a = 0ULL;
            ull hR1a = 0ULL, hZ1a = 0ULL, hN1a = 0ULL;
            ull hR0b = 0ULL, hZ0b = 0ULL, hN0b = 0ULL;
            ull hR1b = 0ULL, hZ1b = 0ULL, hN1b = 0ULL;
            const ulonglong2* wR0 = (const ulonglong2*)(sWhh + g0 * HH);
            const ulonglong2* wZ0 = (const ulonglong2*)(sWhh + (HH + g0) * HH);
            const ulonglong2* wN0 = (const ulonglong2*)(sWhh + (2 * HH + g0) * HH);
            const ulonglong2* wR1 = (const ulonglong2*)(sWhh + g1 * HH);
            const ulonglong2* wZ1 = (const ulonglong2*)(sWhh + (HH + g1) * HH);
            const ulonglong2* wN1 = (const ulonglong2*)(sWhh + (2 * HH + g1) * HH);
#pragma unroll
            for (int q = 0; q < 8; q++) {
                ull ha = h2[2 * q], hb = h2[2 * q + 1];
                ulonglong2 a0 = wR0[q], c0 = wZ0[q], d0 = wN0[q];
                hR0a = ffma2(a0.x, ha, hR0a); hR0a = ffma2(a0.y, hb, hR0a);
                hZ0a = ffma2(c0.x, ha, hZ0a); hZ0a = ffma2(c0.y, hb, hZ0a);
                hN0a = ffma2(d0.x, ha, hN0a); hN0a = ffma2(d0.y, hb, hN0a);
                ulonglong2 a1 = wR1[q], c1 = wZ1[q], d1 = wN1[q];
                hR1a = ffma2(a1.x, ha, hR1a); hR1a = ffma2(a1.y, hb, hR1a);
                hZ1a = ffma2(c1.x, ha, hZ1a); hZ1a = ffma2(c1.y, hb, hZ1a);
                hN1a = ffma2(d1.x, ha, hN1a); hN1a = ffma2(d1.y, hb, hN1a);
            }
#pragma unroll
            for (int q = 8; q < 16; q++) {
                ull ha = h2[2 * q], hb = h2[2 * q + 1];
                ulonglong2 a0 = wR0[q], c0 = wZ0[q], d0 = wN0[q];
                hR0b = ffma2(a0.x, ha, hR0b); hR0b = ffma2(a0.y, hb, hR0b);
                hZ0b = ffma2(c0.x, ha, hZ0b); hZ0b = ffma2(c0.y, hb, hZ0b);
                hN0b = ffma2(d0.x, ha, hN0b); hN0b = ffma2(d0.y, hb, hN0b);
                ulonglong2 a1 = wR1[q], c1 = wZ1[q], d1 = wN1[q];
                hR1b = ffma2(a1.x, ha, hR1b); hR1b = ffma2(a1.y, hb, hR1b);
                hZ1b = ffma2(c1.x, ha, hZ1b); hZ1b = ffma2(c1.y, hb, hZ1b);
                hN1b = ffma2(d1.x, ha, hN1b); hN1b = ffma2(d1.y, hb, hN1b);
            }
            ull hR0 = fadd2(hR0a, hR0b), hZ0 = fadd2(hZ0a, hZ0b), hN0 = fadd2(hN0a, hN0b);
            ull hR1 = fadd2(hR1a, hR1b), hZ1 = fadd2(hZ1a, hZ1b), hN1 = fadd2(hN1a, hN1b);

            float ar0  = sbih[g0] + sbhh[g0] + arx0 + hadd(hR0);
            float az0  = sbih[HH + g0] + sbhh[HH + g0] + azx0 + hadd(hZ0);
            float anx0 = sbih[2 * HH + g0] + anx0s;
            float anh0 = sbhh[2 * HH + g0] + hadd(hN0);
            float ar1  = sbih[g1] + sbhh[g1] + arx1 + hadd(hR1);
            float az1  = sbih[HH + g1] + sbhh[HH + g1] + azx1 + hadd(hZ1);
            float anx1 = sbih[2 * HH + g1] + anx1s;
            float anh1 = sbhh[2 * HH + g1] + hadd(hN1);

            float r0 = fsig(ar0), z0 = fsig(az0);
            float nn0 = ftanh(fmaf(r0, anh0, anx0));
            float r1 = fsig(ar1), z1 = fsig(az1);
            float nn1 = ftanh(fmaf(r1, anh1, anx1));

            float2 holdp = upk(scrAu[gp * ATH + tid]);
            float hn0 = fmaf(z0, holdp.x, (1.0f - z0) * nn0);
            float hn1 = fmaf(z1, holdp.y, (1.0f - z1) * nn1);
            scrAu[gp * ATH + tid] = pk(hn0, hn1);
        }

        float act = mlp_head(sW1, sW2T, sb1, sb2, sW3, sb3[0], scrAu, tid);
        int F = n * (BB * TT) + b * TT + 1;
        g_Aflat[F] = act;
        if (((F / 100) & 1) == 1) out[(F / 200) * 100 + (F % 100)] = act;
    }
}

// ---------------------------------------------------------------------------
// Critic + LocalizedModule: warp-per-batch-row, 16 warps/CTA, grid 128.
// (R11 known-good: preamble-bound; padded strides kill transpose conflicts.)
// ---------------------------------------------------------------------------
__global__ __launch_bounds__(32 * CW, 1)
void critic_kernel(const float* __restrict__ x,
                   const float* __restrict__ lmW1, const float* __restrict__ lmb1,
                   const float* __restrict__ lmW2, const float* __restrict__ lmb2,
                   const float* __restrict__ lmW3, const float* __restrict__ lmb3,
                   const float* __restrict__ scWih, const float* __restrict__ scWhh,
                   const float* __restrict__ scbih, const float* __restrict__ scbhh,
                   const float* __restrict__ scW1,  const float* __restrict__ scb1,
                   const float* __restrict__ scW2,  const float* __restrict__ scb2,
                   const float* __restrict__ scW3,  const float* __restrict__ scb3,
                   float* __restrict__ out)
{
    extern __shared__ float sm[];
    float* sWih = sm;                     // [i][g]  NBF*G3P
    float* sWhh = sWih + NBF * G3P;       // [k][g]  HH*G3P
    float* sW1  = sWhh + HH * G3P;        // [k][j]  HH*HHP
    float* sW2  = sW1 + HH * HHP;         // [k][j]  HH*HHP
    float* sW3  = sW2 + HH * HHP;         // 64
    float* sbih = sW3 + HH;               // 192
    float* sbhh = sbih + G3;              // 192
    float* sb1  = sbhh + G3;              // 64
    float* sb2  = sb1 + HH;               // 64
    float* sb3c = sb2 + HH;               // 4 (1 used)
    float* sLW1 = sb3c + 4;               // [i][j]  NBF*LMP
    float* sLW2 = sLW1 + NBF * LMP;       // [k][j]  LMH*LMP
    float* sLW3 = sLW2 + LMH * LMP;       // 128
    float* sLb1 = sLW3 + LMH;             // 128
    float* sLb2 = sLb1 + LMH;             // 128
    float* sLb3 = sLb2 + LMH;             // 4 (1 used)
    float* sXi  = sLb3 + 4;               // CW * 2*35
    float* sH   = sXi + CW * 2 * NBF;     // CW * 64
    float* sBuf = sH + CW * HH;           // CW * 128

    const int tid = threadIdx.x;
    const int NTH = 32 * CW;

    for (int idx = tid; idx < G3 * NBF; idx += NTH) { int g = idx / NBF, i = idx % NBF; sWih[i * G3P + g] = scWih[idx]; }
    for (int idx = tid; idx < G3 * HH;  idx += NTH) { int g = idx / HH,  k = idx % HH;  sWhh[k * G3P + g] = scWhh[idx]; }
    for (int idx = tid; idx < HH * HH;  idx += NTH) { int j = idx / HH,  k = idx % HH;  sW1[k * HHP + j]  = scW1[idx]; }
    for (int idx = tid; idx < HH * HH;  idx += NTH) { int j = idx / HH,  k = idx % HH;  sW2[k * HHP + j]  = scW2[idx]; }
    for (int idx = tid; idx < LMH * NBF; idx += NTH) { int j = idx / NBF, i = idx % NBF; sLW1[i * LMP + j] = lmW1[idx]; }
    for (int idx = tid; idx < LMH * LMH; idx += NTH) { int j = idx / LMH, k = idx % LMH; sLW2[k * LMP + j] = lmW2[idx]; }
    if (tid < G3)  { sbih[tid] = scbih[tid]; sbhh[tid] = scbhh[tid]; }
    if (tid < HH)  { sW3[tid] = scW3[tid]; sb1[tid] = scb1[tid]; sb2[tid] = scb2[tid]; }
    if (tid < LMH) { sLW3[tid] = lmW3[tid]; sLb1[tid] = lmb1[tid]; sLb2[tid] = lmb2[tid]; }
    if (tid == 0)  { sb3c[0] = scb3[0]; sLb3[0] = lmb3[0]; }
    __syncthreads();

    const int w = tid >> 5, l = tid & 31;
    const int b = blockIdx.x * CW + w;
    float* xi = sXi + w * (2 * NBF);
    float* hs = sH + w * HH;
    float* bf = sBuf + w * LMH;

    // Build xi[t][35]: [xc99(7), xc89(7), zeros(7), zeros(7), xc98(7)]
    for (int i = l; i < NBF; i += 32) {
#pragma unroll
        for (int t = 0; t < TT; t++) {
            float v;
            if (i < 6)        v = x[((b * TT + t) * NZ + 99) * SS + i];
            else if (i == 6)  v = g_Aflat[200 * b + 100 * t + 99];
            else if (i < 13)  v = x[((b * TT + t) * NZ + 89) * SS + (i - 7)];
            else if (i == 13) v = g_Aflat[200 * b + 100 * t + 89];
            else if (i < 28)  v = 0.0f;
            else if (i < 34)  v = x[((b * TT + t) * NZ + 98) * SS + (i - 28)];
            else              v = g_Aflat[200 * b + 100 * t + 98];
            xi[t * NBF + i] = v;
        }
    }
    hs[l] = 0.0f; hs[l + 32] = 0.0f;
    __syncwarp();

    const int u0 = l, u1 = l + 32;

    // --- SubCritic GRU, 2 steps. Lane owns hidden units u0, u1. ---
    for (int t = 0; t < TT; t++) {
        float ar0 = sbih[u0] + sbhh[u0], az0 = sbih[64 + u0] + sbhh[64 + u0];
        float an0 = sbih[128 + u0],      ah0 = sbhh[128 + u0];
        float ar1 = sbih[u1] + sbhh[u1], az1 = sbih[64 + u1] + sbhh[64 + u1];
        float an1 = sbih[128 + u1],      ah1 = sbhh[128 + u1];
        const float* xit = xi + t * NBF;
#pragma unroll
        for (int i = 0; i < NBF; i++) {
            float xv = xit[i];
            const float* wc = sWih + i * G3P;
            ar0 = fmaf(wc[u0],      xv, ar0); az0 = fmaf(wc[64 + u0],  xv, az0); an0 = fmaf(wc[128 + u0], xv, an0);
            ar1 = fmaf(wc[u1],      xv, ar1); az1 = fmaf(wc[64 + u1],  xv, az1); an1 = fmaf(wc[128 + u1], xv, an1);
        }
        // n-gate recurrent term accumulates into ah: n = tanh(xn + r*(Whh_n h + bhh_n))
#pragma unroll
        for (int k = 0; k < HH; k++) {
            float hk = hs[k];
            const float* wc = sWhh + k * G3P;
            ar0 = fmaf(wc[u0],      hk, ar0); az0 = fmaf(wc[64 + u0],  hk, az0); ah0 = fmaf(wc[128 + u0], hk, ah0);
            ar1 = fmaf(wc[u1],      hk, ar1); az1 = fmaf(wc[64 + u1],  hk, az1); ah1 = fmaf(wc[128 + u1], hk, ah1);
        }
        float r0 = fsig(ar0), z0 = fsig(az0), n0 = ftanh(fmaf(r0, ah0, an0));
        float r1 = fsig(ar1), z1 = fsig(az1), n1 = ftanh(fmaf(r1, ah1, an1));
        float hn0 = (1.0f - z0) * n0 + z0 * hs[u0];
        float hn1 = (1.0f - z1) * n1 + z1 * hs[u1];
        __syncwarp();
        hs[u0] = hn0; hs[u1] = hn1;
        __syncwarp();
    }

    // --- q MLP: relu(h) -> 64 -> 64 -> 1 ---
    float a0 = sb1[u0], a1 = sb1[u1];
#pragma unroll
    for (int k = 0; k < HH; k++) {
        float ck = fmaxf(hs[k], 0.0f);
        a0 = fmaf(sW1[k * HHP + u0], ck, a0);
        a1 = fmaf(sW1[k * HHP + u1], ck, a1);
    }
    bf[u0] = fmaxf(a0, 0.0f); bf[u1] = fmaxf(a1, 0.0f);
    __syncwarp();
    a0 = sb2[u0]; a1 = sb2[u1];
#pragma unroll
    for (int k = 0; k < HH; k++) {
        float ck = bf[k];
        a0 = fmaf(sW2[k * HHP + u0], ck, a0);
        a1 = fmaf(sW2[k * HHP + u1], ck, a1);
    }
    float part = sW3[u0] * fmaxf(a0, 0.0f) + sW3[u1] * fmaxf(a1, 0.0f);
#pragma unroll
    for (int off = 16; off > 0; off >>= 1) part += __shfl_xor_sync(0xffffffffu, part, off);
    float q = part + sb3c[0];
    __syncwarp();   // all bf reads done before LM reuses bf

    // --- LocalizedModule on xi[t=1]: 35 -> 128 -> 128 -> 1. Lane owns 4 units. ---
    const int v0 = l, v1 = l + 32, v2 = l + 64, v3 = l + 96;
    float f0 = sLb1[v0], f1 = sLb1[v1], f2 = sLb1[v2], f3 = sLb1[v3];
    const float* xit = xi + NBF;
#pragma unroll
    for (int i = 0; i < NBF; i++) {
        float xv = xit[i];
        const float* wc = sLW1 + i * LMP;
        f0 = fmaf(wc[v0], xv, f0); f1 = fmaf(wc[v1], xv, f1);
        f2 = fmaf(wc[v2], xv, f2); f3 = fmaf(wc[v3], xv, f3);
    }
    bf[v0] = fmaxf(f0, 0.0f); bf[v1] = fmaxf(f1, 0.0f);
    bf[v2] = fmaxf(f2, 0.0f); bf[v3] = fmaxf(f3, 0.0f);
    __syncwarp();
    f0 = sLb2[v0]; f1 = sLb2[v1]; f2 = sLb2[v2]; f3 = sLb2[v3];
#pragma unroll 8
    for (int k = 0; k < LMH; k++) {
        float ck = bf[k];
        const float* wc = sLW2 + k * LMP;
        f0 = fmaf(wc[v0], ck, f0); f1 = fmaf(wc[v1], ck, f1);
        f2 = fmaf(wc[v2], ck, f2); f3 = fmaf(wc[v3], ck, f3);
    }
    float pf = sLW3[v0] * fmaxf(f0, 0.0f) + sLW3[v1] * fmaxf(f1, 0.0f)
             + sLW3[v2] * fmaxf(f2, 0.0f) + sLW3[v3] * fmaxf(f3, 0.0f);
#pragma unroll
    for (int off = 16; off > 0; off >>= 1) pf += __shfl_xor_sync(0xffffffffu, pf, off);

    if (l == 0) out[BB * NZ + b] = (pf + sLb3[0]) + q;
}

// ---------------------------------------------------------------------------
extern "C" void kernel_launch(void* const* d_in, const int* in_sizes, int n_in,
                              void* d_out, int out_size)
{
    const float* x      = (const float*)d_in[0];
    const float* a_Wih  = (const float*)d_in[1];
    const float* a_Whh  = (const float*)d_in[2];
    const float* a_bih  = (const float*)d_in[3];
    const float* a_bhh  = (const float*)d_in[4];
    const float* a_W1   = (const float*)d_in[5];
    const float* a_b1   = (const float*)d_in[6];
    const float* a_W2   = (const float*)d_in[7];
    const float* a_b2   = (const float*)d_in[8];
    const float* a_W3   = (const float*)d_in[9];
    const float* a_b3   = (const float*)d_in[10];
    const float* lm_W1  = (const float*)d_in[11];
    const float* lm_b1  = (const float*)d_in[12];
    const float* lm_W2  = (const float*)d_in[13];
    const float* lm_b2  = (const float*)d_in[14];
    const float* lm_W3  = (const float*)d_in[15];
    const float* lm_b3  = (const float*)d_in[16];
    const float* sc_Wih = (const float*)d_in[17];
    const float* sc_Whh = (const float*)d_in[18];
    const float* sc_bih = (const float*)d_in[19];
    const float* sc_bhh = (const float*)d_in[20];
    const float* sc_W1  = (const float*)d_in[21];
    const float* sc_b1  = (const float*)d_in[22];
    const float* sc_W2  = (const float*)d_in[23];
    const float* sc_b2  = (const float*)d_in[24];
    const float* sc_W3  = (const float*)d_in[25];
    const float* sc_b3  = (const float*)d_in[26];
    float* out = (float*)d_out;

    // Actor SMEM: weights (22212 floats) + packed scratch 32*512*2 floats
    constexpr size_t SMA = (size_t)(12288 + 4096 + 4096 + 1152 + 192 + 192 + 64 + 64 + 64 + 4
                                    + 32 * ATH * 2) * sizeof(float);
    // Critic SMEM (padded strides, CW warps)
    constexpr size_t SMC = (size_t)(NBF*G3P + HH*G3P + HH*HHP + HH*HHP + HH + G3 + G3 + HH + HH + 4
                                    + NBF*LMP + LMH*LMP + LMH + LMH + LMH + 4
                                    + CW * (2*NBF) + CW * HH + CW * LMH) * sizeof(float);

    cudaFuncSetAttribute(actor_kernel,  cudaFuncAttributeMaxDynamicSharedMemorySize, (int)SMA);
    cudaFuncSetAttribute(critic_kernel, cudaFuncAttributeMaxDynamicSharedMemorySize, (int)SMC);

    actor_kernel<<<dim3(BB / ATH, NZ), ATH, SMA>>>(
        x, a_Wih, a_Whh, a_bih, a_bhh, a_W1, a_b1, a_W2, a_b2, a_W3, a_b3, out);

    critic_kernel<<<BB / CW, 32 * CW, SMC>>>(
        x, lm_W1, lm_b1, lm_W2, lm_b2, lm_W3, lm_b3,
        sc_Wih, sc_Whh, sc_bih, sc_bhh, sc_W1, sc_b1, sc_W2, sc_b2, sc_W3, sc_b3,
        out);
}

// round 16
// speedup vs baseline: 1.2624x; 1.0030x over previous
#include <cuda_runtime.h>

// Problem constants
#define BB  2048   // batch
#define TT  2      // timesteps
#define NZ  100    // zones
#define SS  6      // state
#define HH  64     // hidden (actor + critic)
#define G3  192    // 3*H gate rows
#define NBF 35     // neighbor feature size
#define LMH 128    // localized module hidden
#define ATH 512    // actor threads per CTA == batch tile
#define CW  16     // critic warps per CTA
// padded strides (critic SMEM, kill 32-way write conflicts)
#define G3P 193
#define HHP 65
#define LMP 129

typedef unsigned long long ull;

// Actor output scratch, layout Aflat[n*(B*T) + b*T + t]  (== flatten of [N,B,T])
//   p[b,t,n] = Aflat[200*b + 100*t + n]
// The reshape scramble makes EVERY Aflat entry live in output 0 (R8 lesson).
// Fused p-output inverse map: element F=4096n+2b+t is out_p[F/200, F%100]
// iff (F/100) is odd.
__device__ float g_Aflat[NZ * BB * TT];

__device__ __forceinline__ float fsig(float x) {
    return __fdividef(1.0f, 1.0f + __expf(-x));
}
__device__ __forceinline__ float ftanh(float x) {
    return 1.0f - __fdividef(2.0f, __expf(2.0f * x) + 1.0f);
}
// packed f32x2 helpers (Blackwell)
__device__ __forceinline__ ull pk(float a, float b) {
    ull r; asm("mov.b64 %0,{%1,%2};" : "=l"(r) : "f"(a), "f"(b)); return r;
}
__device__ __forceinline__ float2 upk(ull v) {
    float2 r; asm("mov.b64 {%0,%1},%2;" : "=f"(r.x), "=f"(r.y) : "l"(v)); return r;
}
__device__ __forceinline__ ull ffma2(ull a, ull b, ull c) {   // a*b+c, 2 lanes
    ull d; asm("fma.rn.f32x2 %0,%1,%2,%3;" : "=l"(d) : "l"(a), "l"(b), "l"(c)); return d;
}
__device__ __forceinline__ ull fadd2(ull a, ull b) {
    ull d; asm("add.rn.f32x2 %0,%1,%2;" : "=l"(d) : "l"(a), "l"(b)); return d;
}
__device__ __forceinline__ float hadd(ull v) { float2 t = upk(v); return t.x + t.y; }

// ---------------------------------------------------------------------------
// Fused actor MLP head: relu(h)->64->relu->64->relu->1, h packed in scrA.
// Layer1 in 4 blocks of 16 gates: h re-read 4x. (R15 winner, untouched.)
// ---------------------------------------------------------------------------
__device__ __forceinline__ float mlp_head(const float* __restrict__ sW1,
                                          const float* __restrict__ sW2T,
                                          const float* __restrict__ sb1,
                                          const float* __restrict__ sb2,
                                          const float* __restrict__ sW3,
                                          float b3v,
                                          const ull* __restrict__ scrAu,
                                          int tid)
{
    ull acc2[32];
    const ull* sb2u = (const ull*)sb2;
#pragma unroll
    for (int jp = 0; jp < 32; jp++) acc2[jp] = sb2u[jp];

    for (int gb = 0; gb < 4; gb++) {
        ull a1p[16];
#pragma unroll
        for (int j = 0; j < 16; j++) a1p[j] = 0ULL;
#pragma unroll 4
        for (int kp = 0; kp < 32; kp += 2) {
            float2 va = upk(scrAu[kp * ATH + tid]);
            float2 vb = upk(scrAu[(kp + 1) * ATH + tid]);
            ull vva = pk(fmaxf(va.x, 0.0f), fmaxf(va.y, 0.0f));
            ull vvb = pk(fmaxf(vb.x, 0.0f), fmaxf(vb.y, 0.0f));
#pragma unroll
            for (int j = 0; j < 16; j++) {
                ulonglong2 w = ((const ulonglong2*)(sW1 + (gb * 16 + j) * HH))[kp >> 1];
                a1p[j] = ffma2(w.x, vva, a1p[j]);
                a1p[j] = ffma2(w.y, vvb, a1p[j]);
            }
        }
        float a1[16];
#pragma unroll
        for (int j = 0; j < 16; j++) a1[j] = fmaxf(hadd(a1p[j]) + sb1[gb * 16 + j], 0.0f);
#pragma unroll
        for (int kk = 0; kk < 16; kk++) {
            ull s = pk(a1[kk], a1[kk]);
            const ulonglong2* w2 = (const ulonglong2*)(sW2T + (gb * 16 + kk) * HH);
#pragma unroll
            for (int jq = 0; jq < 16; jq++) {
                ulonglong2 w = w2[jq];
                acc2[2 * jq]     = ffma2(w.x, s, acc2[2 * jq]);
                acc2[2 * jq + 1] = ffma2(w.y, s, acc2[2 * jq + 1]);
            }
        }
    }
    float acc = b3v;
#pragma unroll
    for (int jp = 0; jp < 32; jp++) {
        float2 a = upk(acc2[jp]);
        acc = fmaf(sW3[2 * jp],     fmaxf(a.x, 0.0f), acc);
        acc = fmaf(sW3[2 * jp + 1], fmaxf(a.y, 0.0f), acc);
    }
    return 3.0f * (fsig(acc) - 0.5f);
}

// ---------------------------------------------------------------------------
// Actor: one CTA per (zone n, 512-batch tile). Thread = one batch row.
// (R15 winner, untouched.)
// ---------------------------------------------------------------------------
__global__ __launch_bounds__(ATH, 1)
void actor_kernel(const float* __restrict__ x,
                  const float* __restrict__ Wih, const float* __restrict__ Whh,
                  const float* __restrict__ bih, const float* __restrict__ bhh,
                  const float* __restrict__ W1,  const float* __restrict__ b1,
                  const float* __restrict__ W2,  const float* __restrict__ b2,
                  const float* __restrict__ W3,  const float* __restrict__ b3,
                  float* __restrict__ out)
{
    extern __shared__ float sm[];
    float* sWhh = sm;                   // 12288  [g][k] row-major
    float* sW1  = sWhh + G3 * HH;       // 4096   [g][k]
    float* sW2T = sW1 + HH * HH;        // 4096   [k][j] transposed
    float* sWih = sW2T + HH * HH;       // 1152   [g][s]
    float* sbih = sWih + G3 * SS;       // 192
    float* sbhh = sbih + G3;            // 192
    float* sb1  = sbhh + G3;            // 64
    float* sb2  = sb1 + HH;             // 64
    float* sW3  = sb2 + HH;             // 64
    float* sb3  = sW3 + HH;             // 4 (1 used)
    float* scrAf = sb3 + 4;             // 32*512 float2 (packed h)
    ull*   scrAu = (ull*)scrAf;

    const int n   = blockIdx.y;
    const int tid = threadIdx.x;
    const int b   = blockIdx.x * ATH + tid;

    for (int i = tid; i < G3 * HH; i += ATH) sWhh[i] = Whh[n * G3 * HH + i];
    for (int i = tid; i < HH * HH; i += ATH) sW1[i]  = W1[n * HH * HH + i];
    for (int i = tid; i < HH * HH; i += ATH) { int j = i >> 6, k = i & 63; sW2T[k * HH + j] = W2[n * HH * HH + i]; }
    for (int i = tid; i < G3 * SS; i += ATH) sWih[i] = Wih[n * G3 * SS + i];
    if (tid < G3) { sbih[tid] = bih[n * G3 + tid]; sbhh[tid] = bhh[n * G3 + tid]; }
    if (tid < HH) { sb1[tid] = b1[n * HH + tid]; sb2[tid] = b2[n * HH + tid]; sW3[tid] = W3[n * HH + tid]; }
    if (tid == 0) sb3[0] = b3[n];
    __syncthreads();

    // ======================= t = 0 (h0 == 0: no Whh work) =======================
    {
        const float* xr = x + ((size_t)(b * TT + 0) * NZ + n) * SS;
        float2 x0 = *(const float2*)xr, x1 = *(const float2*)(xr + 2), x2 = *(const float2*)(xr + 4);
        ull xp0 = pk(x0.x, x0.y), xp1 = pk(x1.x, x1.y), xp2 = pk(x2.x, x2.y);

#pragma unroll 2
        for (int gp = 0; gp < 32; gp++) {
            const int g0 = gp * 2, g1 = g0 + 1;
            const ull* wr0 = (const ull*)(sWih + g0 * SS);
            const ull* wz0 = (const ull*)(sWih + (HH + g0) * SS);
            const ull* wn0 = (const ull*)(sWih + (2 * HH + g0) * SS);
            const ull* wr1 = (const ull*)(sWih + g1 * SS);
            const ull* wz1 = (const ull*)(sWih + (HH + g1) * SS);
            const ull* wn1 = (const ull*)(sWih + (2 * HH + g1) * SS);
            ull aR0 = ffma2(wr0[0], xp0, ffma2(wr0[1], xp1, ffma2(wr0[2], xp2, 0ULL)));
            ull aZ0 = ffma2(wz0[0], xp0, ffma2(wz0[1], xp1, ffma2(wz0[2], xp2, 0ULL)));
            ull aN0 = ffma2(wn0[0], xp0, ffma2(wn0[1], xp1, ffma2(wn0[2], xp2, 0ULL)));
            ull aR1 = ffma2(wr1[0], xp0, ffma2(wr1[1], xp1, ffma2(wr1[2], xp2, 0ULL)));
            ull aZ1 = ffma2(wz1[0], xp0, ffma2(wz1[1], xp1, ffma2(wz1[2], xp2, 0ULL)));
            ull aN1 = ffma2(wn1[0], xp0, ffma2(wn1[1], xp1, ffma2(wn1[2], xp2, 0ULL)));

            float ar0  = sbih[g0] + sbhh[g0] + hadd(aR0);
            float az0  = sbih[HH + g0] + sbhh[HH + g0] + hadd(aZ0);
            float anx0 = sbih[2 * HH + g0] + hadd(aN0);
            float anh0 = sbhh[2 * HH + g0];
            float ar1  = sbih[g1] + sbhh[g1] + hadd(aR1);
            float az1  = sbih[HH + g1] + sbhh[HH + g1] + hadd(aZ1);
            float anx1 = sbih[2 * HH + g1] + hadd(aN1);
            float anh1 = sbhh[2 * HH + g1];

            float r0 = fsig(ar0), z0 = fsig(az0);
            float nn0 = ftanh(fmaf(r0, anh0, anx0));
            float r1 = fsig(ar1), z1 = fsig(az1);
            float nn1 = ftanh(fmaf(r1, anh1, anx1));
            scrAu[gp * ATH + tid] = pk((1.0f - z0) * nn0, (1.0f - z1) * nn1);
        }

        float act = mlp_head(sW1, sW2T, sb1, sb2, sW3, sb3[0], scrAu, tid);
        int F = n * (BB * TT) + b * TT + 0;
        g_Aflat[F] = act;
        if (((F / 100) & 1) == 1) out[(F / 200) * 100 + (F % 100)] = act;
    }

    // ======================= t = 1 (full GRU step) =======================
    {
        ull h2[32];
#pragma unroll
        for (int kp = 0; kp < 32; kp++) h2[kp] = scrAu[kp * ATH + tid];

        const float* xr = x + ((size_t)(b * TT + 1) * NZ + n) * SS;
        float2 x0 = *(const float2*)xr, x1 = *(const float2*)(xr + 2), x2 = *(const float2*)(xr + 4);
        ull xp0 = pk(x0.x, x0.y), xp1 = pk(x1.x, x1.y), xp2 = pk(x2.x, x2.y);

#pragma unroll 1
        for (int gp = 0; gp < 32; gp++) {
            const int g0 = gp * 2, g1 = g0 + 1;
            const ull* wr0 = (const ull*)(sWih + g0 * SS);
            const ull* wz0 = (const ull*)(sWih + (HH + g0) * SS);
            const ull* wn0 = (const ull*)(sWih + (2 * HH + g0) * SS);
            const ull* wr1 = (const ull*)(sWih + g1 * SS);
            const ull* wz1 = (const ull*)(sWih + (HH + g1) * SS);
            const ull* wn1 = (const ull*)(sWih + (2 * HH + g1) * SS);
            ull aR0 = ffma2(wr0[0], xp0, ffma2(wr0[1], xp1, ffma2(wr0[2], xp2, 0ULL)));
            ull aZ0 = ffma2(wz0[0], xp0, ffma2(wz0[1], xp1, ffma2(wz0[2], xp2, 0ULL)));
            ull aN0 = ffma2(wn0[0], xp0, ffma2(wn0[1], xp1, ffma2(wn0[2], xp2, 0ULL)));
            ull aR1 = ffma2(wr1[0], xp0, ffma2(wr1[1], xp1, ffma2(wr1[2], xp2, 0ULL)));
            ull aZ1 = ffma2(wz1[0], xp0, ffma2(wz1[1], xp1, ffma2(wz1[2], xp2, 0ULL)));
            ull aN1 = ffma2(wn1[0], xp0, ffma2(wn1[1], xp1, ffma2(wn1[2], xp2, 0ULL)));
            float arx0 = hadd(aR0), azx0 = hadd(aZ0), anx0s = hadd(aN0);
            float arx1 = hadd(aR1), azx1 = hadd(aZ1), anx1s = hadd(aN1);

            // 2-way split accumulator chains (halved dependency depth).
            ull hR0a = 0ULL, hZ0a = 0ULL, hN0a = 0ULL;
            ull hR1a = 0ULL, hZ1a = 0ULL, hN1a = 0ULL;
            ull hR0b = 0ULL, hZ0b = 0ULL, hN0b = 0ULL;
            ull hR1b = 0ULL, hZ1b = 0ULL, hN1b = 0ULL;
            const ulonglong2* wR0 = (const ulonglong2*)(sWhh + g0 * HH);
            const ulonglong2* wZ0 = (const ulonglong2*)(sWhh + (HH + g0) * HH);
            const ulonglong2* wN0 = (const ulonglong2*)(sWhh + (2 * HH + g0) * HH);
            const ulonglong2* wR1 = (const ulonglong2*)(sWhh + g1 * HH);
            const ulonglong2* wZ1 = (const ulonglong2*)(sWhh + (HH + g1) * HH);
            const ulonglong2* wN1 = (const ulonglong2*)(sWhh + (2 * HH + g1) * HH);
#pragma unroll
            for (int q = 0; q < 8; q++) {
                ull ha = h2[2 * q], hb = h2[2 * q + 1];
                ulonglong2 a0 = wR0[q], c0 = wZ0[q], d0 = wN0[q];
                hR0a = ffma2(a0.x, ha, hR0a); hR0a = ffma2(a0.y, hb, hR0a);
                hZ0a = ffma2(c0.x, ha, hZ0a); hZ0a = ffma2(c0.y, hb, hZ0a);
                hN0a = ffma2(d0.x, ha, hN0a); hN0a = ffma2(d0.y, hb, hN0a);
                ulonglong2 a1 = wR1[q], c1 = wZ1[q], d1 = wN1[q];
                hR1a = ffma2(a1.x, ha, hR1a); hR1a = ffma2(a1.y, hb, hR1a);
                hZ1a = ffma2(c1.x, ha, hZ1a); hZ1a = ffma2(c1.y, hb, hZ1a);
                hN1a = ffma2(d1.x, ha, hN1a); hN1a = ffma2(d1.y, hb, hN1a);
            }
#pragma unroll
            for (int q = 8; q < 16; q++) {
                ull ha = h2[2 * q], hb = h2[2 * q + 1];
                ulonglong2 a0 = wR0[q], c0 = wZ0[q], d0 = wN0[q];
                hR0b = ffma2(a0.x, ha, hR0b); hR0b = ffma2(a0.y, hb, hR0b);
                hZ0b = ffma2(c0.x, ha, hZ0b); hZ0b = ffma2(c0.y, hb, hZ0b);
                hN0b = ffma2(d0.x, ha, hN0b); hN0b = ffma2(d0.y, hb, hN0b);
                ulonglong2 a1 = wR1[q], c1 = wZ1[q], d1 = wN1[q];
                hR1b = ffma2(a1.x, ha, hR1b); hR1b = ffma2(a1.y, hb, hR1b);
                hZ1b = ffma2(c1.x, ha, hZ1b); hZ1b = ffma2(c1.y, hb, hZ1b);
                hN1b = ffma2(d1.x, ha, hN1b); hN1b = ffma2(d1.y, hb, hN1b);
            }
            ull hR0 = fadd2(hR0a, hR0b), hZ0 = fadd2(hZ0a, hZ0b), hN0 = fadd2(hN0a, hN0b);
            ull hR1 = fadd2(hR1a, hR1b), hZ1 = fadd2(hZ1a, hZ1b), hN1 = fadd2(hN1a, hN1b);

            float ar0  = sbih[g0] + sbhh[g0] + arx0 + hadd(hR0);
            float az0  = sbih[HH + g0] + sbhh[HH + g0] + azx0 + hadd(hZ0);
            float anx0 = sbih[2 * HH + g0] + anx0s;
            float anh0 = sbhh[2 * HH + g0] + hadd(hN0);
            float ar1  = sbih[g1] + sbhh[g1] + arx1 + hadd(hR1);
            float az1  = sbih[HH + g1] + sbhh[HH + g1] + azx1 + hadd(hZ1);
            float anx1 = sbih[2 * HH + g1] + anx1s;
            float anh1 = sbhh[2 * HH + g1] + hadd(hN1);

            float r0 = fsig(ar0), z0 = fsig(az0);
            float nn0 = ftanh(fmaf(r0, anh0, anx0));
            float r1 = fsig(ar1), z1 = fsig(az1);
            float nn1 = ftanh(fmaf(r1, anh1, anx1));

            float2 holdp = upk(scrAu[gp * ATH + tid]);
            float hn0 = fmaf(z0, holdp.x, (1.0f - z0) * nn0);
            float hn1 = fmaf(z1, holdp.y, (1.0f - z1) * nn1);
            scrAu[gp * ATH + tid] = pk(hn0, hn1);
        }

        float act = mlp_head(sW1, sW2T, sb1, sb2, sW3, sb3[0], scrAu, tid);
        int F = n * (BB * TT) + b * TT + 1;
        g_Aflat[F] = act;
        if (((F / 100) & 1) == 1) out[(F / 200) * 100 + (F % 100)] = act;
    }
}

// ---------------------------------------------------------------------------
// Critic + LocalizedModule: warp-per-batch-row, 16 warps/CTA, grid 128.
// Preamble rewritten with explicit (row,col) loops: NO div/mod (R16 change).
// Data placement identical to R15 => bit-identical results.
// ---------------------------------------------------------------------------
__global__ __launch_bounds__(32 * CW, 1)
void critic_kernel(const float* __restrict__ x,
                   const float* __restrict__ lmW1, const float* __restrict__ lmb1,
                   const float* __restrict__ lmW2, const float* __restrict__ lmb2,
                   const float* __restrict__ lmW3, const float* __restrict__ lmb3,
                   const float* __restrict__ scWih, const float* __restrict__ scWhh,
                   const float* __restrict__ scbih, const float* __restrict__ scbhh,
                   const float* __restrict__ scW1,  const float* __restrict__ scb1,
                   const float* __restrict__ scW2,  const float* __restrict__ scb2,
                   const float* __restrict__ scW3,  const float* __restrict__ scb3,
                   float* __restrict__ out)
{
    extern __shared__ float sm[];
    float* sWih = sm;                     // [i][g]  NBF*G3P
    float* sWhh = sWih + NBF * G3P;       // [k][g]  HH*G3P
    float* sW1  = sWhh + HH * G3P;        // [k][j]  HH*HHP
    float* sW2  = sW1 + HH * HHP;         // [k][j]  HH*HHP
    float* sW3  = sW2 + HH * HHP;         // 64
    float* sbih = sW3 + HH;               // 192
    float* sbhh = sbih + G3;              // 192
    float* sb1  = sbhh + G3;              // 64
    float* sb2  = sb1 + HH;               // 64
    float* sb3c = sb2 + HH;               // 4 (1 used)
    float* sLW1 = sb3c + 4;               // [i][j]  NBF*LMP
    float* sLW2 = sLW1 + NBF * LMP;       // [k][j]  LMH*LMP
    float* sLW3 = sLW2 + LMH * LMP;       // 128
    float* sLb1 = sLW3 + LMH;             // 128
    float* sLb2 = sLb1 + LMH;             // 128
    float* sLb3 = sLb2 + LMH;             // 4 (1 used)
    float* sXi  = sLb3 + 4;               // CW * 2*35
    float* sH   = sXi + CW * 2 * NBF;     // CW * 64
    float* sBuf = sH + CW * HH;           // CW * 128

    const int tid = threadIdx.x;
    const int w = tid >> 5, l = tid & 31;

    // --- Weight staging: row = warp-strided, col = lane-strided; no div/mod ---
    // sWih[i][g] <- scWih[g][i]   (G3 x NBF)
    for (int g = w; g < G3; g += CW) {
        const float* src = scWih + g * NBF;
        for (int i = l; i < NBF; i += 32) sWih[i * G3P + g] = src[i];
    }
    // sWhh[k][g] <- scWhh[g][k]   (G3 x HH)
    for (int g = w; g < G3; g += CW) {
        const float* src = scWhh + g * HH;
        sWhh[l * G3P + g]        = src[l];
        sWhh[(l + 32) * G3P + g] = src[l + 32];
    }
    // sW1[k][j] <- scW1[j][k], sW2[k][j] <- scW2[j][k]   (HH x HH)
    for (int j = w; j < HH; j += CW) {
        const float* s1 = scW1 + j * HH;
        const float* s2 = scW2 + j * HH;
        sW1[l * HHP + j]        = s1[l];
        sW1[(l + 32) * HHP + j] = s1[l + 32];
        sW2[l * HHP + j]        = s2[l];
        sW2[(l + 32) * HHP + j] = s2[l + 32];
    }
    // sLW1[i][j] <- lmW1[j][i]   (LMH x NBF)
    for (int j = w; j < LMH; j += CW) {
        const float* src = lmW1 + j * NBF;
        for (int i = l; i < NBF; i += 32) sLW1[i * LMP + j] = src[i];
    }
    // sLW2[k][j] <- lmW2[j][k]   (LMH x LMH)
    for (int j = w; j < LMH; j += CW) {
        const float* src = lmW2 + j * LMH;
        sLW2[l * LMP + j]         = src[l];
        sLW2[(l + 32) * LMP + j]  = src[l + 32];
        sLW2[(l + 64) * LMP + j]  = src[l + 64];
        sLW2[(l + 96) * LMP + j]  = src[l + 96];
    }
    if (tid < G3)  { sbih[tid] = scbih[tid]; sbhh[tid] = scbhh[tid]; }
    if (tid < HH)  { sW3[tid] = scW3[tid]; sb1[tid] = scb1[tid]; sb2[tid] = scb2[tid]; }
    if (tid < LMH) { sLW3[tid] = lmW3[tid]; sLb1[tid] = lmb1[tid]; sLb2[tid] = lmb2[tid]; }
    if (tid == 0)  { sb3c[0] = scb3[0]; sLb3[0] = lmb3[0]; }
    __syncthreads();

    const int b = blockIdx.x * CW + w;
    float* xi = sXi + w * (2 * NBF);
    float* hs = sH + w * HH;
    float* bf = sBuf + w * LMH;

    // Build xi[t][35]: [xc99(7), xc89(7), zeros(7), zeros(7), xc98(7)]
    for (int i = l; i < NBF; i += 32) {
#pragma unroll
        for (int t = 0; t < TT; t++) {
            float v;
            if (i < 6)        v = x[((b * TT + t) * NZ + 99) * SS + i];
            else if (i == 6)  v = g_Aflat[200 * b + 100 * t + 99];
            else if (i < 13)  v = x[((b * TT + t) * NZ + 89) * SS + (i - 7)];
            else if (i == 13) v = g_Aflat[200 * b + 100 * t + 89];
            else if (i < 28)  v = 0.0f;
            else if (i < 34)  v = x[((b * TT + t) * NZ + 98) * SS + (i - 28)];
            else              v = g_Aflat[200 * b + 100 * t + 98];
            xi[t * NBF + i] = v;
        }
    }
    hs[l] = 0.0f; hs[l + 32] = 0.0f;
    __syncwarp();

    const int u0 = l, u1 = l + 32;

    // --- SubCritic GRU, 2 steps. Lane owns hidden units u0, u1. ---
    for (int t = 0; t < TT; t++) {
        float ar0 = sbih[u0] + sbhh[u0], az0 = sbih[64 + u0] + sbhh[64 + u0];
        float an0 = sbih[128 + u0],      ah0 = sbhh[128 + u0];
        float ar1 = sbih[u1] + sbhh[u1], az1 = sbih[64 + u1] + sbhh[64 + u1];
        float an1 = sbih[128 + u1],      ah1 = sbhh[128 + u1];
        const float* xit = xi + t * NBF;
#pragma unroll
        for (int i = 0; i < NBF; i++) {
            float xv = xit[i];
            const float* wc = sWih + i * G3P;
            ar0 = fmaf(wc[u0],      xv, ar0); az0 = fmaf(wc[64 + u0],  xv, az0); an0 = fmaf(wc[128 + u0], xv, an0);
            ar1 = fmaf(wc[u1],      xv, ar1); az1 = fmaf(wc[64 + u1],  xv, az1); an1 = fmaf(wc[128 + u1], xv, an1);
        }
        // n-gate recurrent term accumulates into ah: n = tanh(xn + r*(Whh_n h + bhh_n))
#pragma unroll
        for (int k = 0; k < HH; k++) {
            float hk = hs[k];
            const float* wc = sWhh + k * G3P;
            ar0 = fmaf(wc[u0],      hk, ar0); az0 = fmaf(wc[64 + u0],  hk, az0); ah0 = fmaf(wc[128 + u0], hk, ah0);
            ar1 = fmaf(wc[u1],      hk, ar1); az1 = fmaf(wc[64 + u1],  hk, az1); ah1 = fmaf(wc[128 + u1], hk, ah1);
        }
        float r0 = fsig(ar0), z0 = fsig(az0), n0 = ftanh(fmaf(r0, ah0, an0));
        float r1 = fsig(ar1), z1 = fsig(az1), n1 = ftanh(fmaf(r1, ah1, an1));
        float hn0 = (1.0f - z0) * n0 + z0 * hs[u0];
        float hn1 = (1.0f - z1) * n1 + z1 * hs[u1];
        __syncwarp();
        hs[u0] = hn0; hs[u1] = hn1;
        __syncwarp();
    }

    // --- q MLP: relu(h) -> 64 -> 64 -> 1 ---
    float a0 = sb1[u0], a1 = sb1[u1];
#pragma unroll
    for (int k = 0; k < HH; k++) {
        float ck = fmaxf(hs[k], 0.0f);
        a0 = fmaf(sW1[k * HHP + u0], ck, a0);
        a1 = fmaf(sW1[k * HHP + u1], ck, a1);
    }
    bf[u0] = fmaxf(a0, 0.0f); bf[u1] = fmaxf(a1, 0.0f);
    __syncwarp();
    a0 = sb2[u0]; a1 = sb2[u1];
#pragma unroll
    for (int k = 0; k < HH; k++) {
        float ck = bf[k];
        a0 = fmaf(sW2[k * HHP + u0], ck, a0);
        a1 = fmaf(sW2[k * HHP + u1], ck, a1);
    }
    float part = sW3[u0] * fmaxf(a0, 0.0f) + sW3[u1] * fmaxf(a1, 0.0f);
#pragma unroll
    for (int off = 16; off > 0; off >>= 1) part += __shfl_xor_sync(0xffffffffu, part, off);
    float q = part + sb3c[0];
    __syncwarp();   // all bf reads done before LM reuses bf

    // --- LocalizedModule on xi[t=1]: 35 -> 128 -> 128 -> 1. Lane owns 4 units. ---
    const int v0 = l, v1 = l + 32, v2 = l + 64, v3 = l + 96;
    float f0 = sLb1[v0], f1 = sLb1[v1], f2 = sLb1[v2], f3 = sLb1[v3];
    const float* xit = xi + NBF;
#pragma unroll
    for (int i = 0; i < NBF; i++) {
        float xv = xit[i];
        const float* wc = sLW1 + i * LMP;
        f0 = fmaf(wc[v0], xv, f0); f1 = fmaf(wc[v1], xv, f1);
        f2 = fmaf(wc[v2], xv, f2); f3 = fmaf(wc[v3], xv, f3);
    }
    bf[v0] = fmaxf(f0, 0.0f); bf[v1] = fmaxf(f1, 0.0f);
    bf[v2] = fmaxf(f2, 0.0f); bf[v3] = fmaxf(f3, 0.0f);
    __syncwarp();
    f0 = sLb2[v0]; f1 = sLb2[v1]; f2 = sLb2[v2]; f3 = sLb2[v3];
#pragma unroll 8
    for (int k = 0; k < LMH; k++) {
        float ck = bf[k];
        const float* wc = sLW2 + k * LMP;
        f0 = fmaf(wc[v0], ck, f0); f1 = fmaf(wc[v1], ck, f1);
        f2 = fmaf(wc[v2], ck, f2); f3 = fmaf(wc[v3], ck, f3);
    }
    float pf = sLW3[v0] * fmaxf(f0, 0.0f) + sLW3[v1] * fmaxf(f1, 0.0f)
             + sLW3[v2] * fmaxf(f2, 0.0f) + sLW3[v3] * fmaxf(f3, 0.0f);
#pragma unroll
    for (int off = 16; off > 0; off >>= 1) pf += __shfl_xor_sync(0xffffffffu, pf, off);

    if (l == 0) out[BB * NZ + b] = (pf + sLb3[0]) + q;
}

// ---------------------------------------------------------------------------
extern "C" void kernel_launch(void* const* d_in, const int* in_sizes, int n_in,
                              void* d_out, int out_size)
{
    const float* x      = (const float*)d_in[0];
    const float* a_Wih  = (const float*)d_in[1];
    const float* a_Whh  = (const float*)d_in[2];
    const float* a_bih  = (const float*)d_in[3];
    const float* a_bhh  = (const float*)d_in[4];
    const float* a_W1   = (const float*)d_in[5];
    const float* a_b1   = (const float*)d_in[6];
    const float* a_W2   = (const float*)d_in[7];
    const float* a_b2   = (const float*)d_in[8];
    const float* a_W3   = (const float*)d_in[9];
    const float* a_b3   = (const float*)d_in[10];
    const float* lm_W1  = (const float*)d_in[11];
    const float* lm_b1  = (const float*)d_in[12];
    const float* lm_W2  = (const float*)d_in[13];
    const float* lm_b2  = (const float*)d_in[14];
    const float* lm_W3  = (const float*)d_in[15];
    const float* lm_b3  = (const float*)d_in[16];
    const float* sc_Wih = (const float*)d_in[17];
    const float* sc_Whh = (const float*)d_in[18];
    const float* sc_bih = (const float*)d_in[19];
    const float* sc_bhh = (const float*)d_in[20];
    const float* sc_W1  = (const float*)d_in[21];
    const float* sc_b1  = (const float*)d_in[22];
    const float* sc_W2  = (const float*)d_in[23];
    const float* sc_b2  = (const float*)d_in[24];
    const float* sc_W3  = (const float*)d_in[25];
    const float* sc_b3  = (const float*)d_in[26];
    float* out = (float*)d_out;

    // Actor SMEM: weights (22212 floats) + packed scratch 32*512*2 floats
    constexpr size_t SMA = (size_t)(12288 + 4096 + 4096 + 1152 + 192 + 192 + 64 + 64 + 64 + 4
                                    + 32 * ATH * 2) * sizeof(float);
    // Critic SMEM (padded strides, CW warps)
    constexpr size_t SMC = (size_t)(NBF*G3P + HH*G3P + HH*HHP + HH*HHP + HH + G3 + G3 + HH + HH + 4
                                    + NBF*LMP + LMH*LMP + LMH + LMH + LMH + 4
                                    + CW * (2*NBF) + CW * HH + CW * LMH) * sizeof(float);

    cudaFuncSetAttribute(actor_kernel,  cudaFuncAttributeMaxDynamicSharedMemorySize, (int)SMA);
    cudaFuncSetAttribute(critic_kernel, cudaFuncAttributeMaxDynamicSharedMemorySize, (int)SMC);

    actor_kernel<<<dim3(BB / ATH, NZ), ATH, SMA>>>(
        x, a_Wih, a_Whh, a_bih, a_bhh, a_W1, a_b1, a_W2, a_b2, a_W3, a_b3, out);

    critic_kernel<<<BB / CW, 32 * CW, SMC>>>(
        x, lm_W1, lm_b1, lm_W2, lm_b2, lm_W3, lm_b3,
        sc_Wih, sc_Whh, sc_bih, sc_bhh, sc_W1, sc_b1, sc_W2, sc_b2, sc_W3, sc_b3,
        out);
}